// round 3
// baseline (speedup 1.0000x reference)
#include <cuda_runtime.h>
#include <cuda_bf16.h>
#include <stdint.h>

#define N_NODES 20000
#define D_IN    128
#define D_H     256
#define LN_EPS  1e-5f

// ---------------- scratch (no dynamic allocation allowed) ----------------
__device__ float g_deg [N_NODES];
__device__ float g_dinv[N_NODES];
__device__ float g_h1  [N_NODES * D_H];  // x@W1, later h@W2
__device__ float g_agg [N_NODES * D_H];  // scatter accumulator (both hops)
__device__ float g_hres[N_NODES * D_H];  // x@Wres + bres
__device__ float g_h   [N_NODES * D_H];  // after LN1

// ---------------- helpers ----------------
__device__ __forceinline__ void red_add_v4(float4* addr, float4 v) {
    asm volatile("red.global.add.v4.f32 [%0], {%1,%2,%3,%4};"
                 :: "l"(addr), "f"(v.x), "f"(v.y), "f"(v.z), "f"(v.w)
                 : "memory");
}

// ---------------- init: deg = 1 (self loop), agg = 0 ----------------
__global__ void init_kernel() {
    int total = N_NODES * D_H;
    for (int i = blockIdx.x * blockDim.x + threadIdx.x; i < total;
         i += gridDim.x * blockDim.x) {
        g_agg[i] = 0.0f;
        if (i < N_NODES) g_deg[i] = 1.0f;
    }
}

// ---------------- degree accumulation over edges ----------------
__global__ void deg_kernel(const int* __restrict__ dst,
                           const float* __restrict__ w, int E) {
    for (int e = blockIdx.x * blockDim.x + threadIdx.x; e < E;
         e += gridDim.x * blockDim.x) {
        atomicAdd(&g_deg[dst[e]], w[e]);
    }
}

__global__ void dinv_kernel() {
    for (int i = blockIdx.x * blockDim.x + threadIdx.x; i < N_NODES;
         i += gridDim.x * blockDim.x) {
        float d = g_deg[i];
        g_dinv[i] = d > 0.0f ? rsqrtf(d) : 0.0f;
    }
}

// ---------------- tiled fp32 GEMM: C[M,256] = A[M,K] @ B[K,256] (+bias) -----
// BM=64 BN=64 BK=16, 256 threads, 4x4 per thread
template<int K, bool HAS_BIAS>
__global__ void sgemm_kernel(const float* __restrict__ A,
                             const float* __restrict__ B,
                             const float* __restrict__ bias,
                             float* __restrict__ C, int M) {
    __shared__ float As[16][64];
    __shared__ float Bs[16][64];

    const int tid = threadIdx.x;
    const int tx = tid & 15;          // 0..15 -> output cols tx*4..tx*4+3
    const int ty = tid >> 4;          // 0..15 -> output rows ty*4..ty*4+3
    const int bm = blockIdx.x * 64;
    const int bn = blockIdx.y * 64;

    const int a_row = tid >> 2;       // 0..63
    const int a_k4  = tid & 3;        // 0..3  (float4 along K-tile)
    const int b_kr  = tid >> 4;       // 0..15
    const int b_c4  = tid & 15;       // 0..15

    float acc[4][4];
#pragma unroll
    for (int i = 0; i < 4; i++)
#pragma unroll
        for (int j = 0; j < 4; j++) acc[i][j] = 0.0f;

    for (int kt = 0; kt < K; kt += 16) {
        float4 av = make_float4(0.f, 0.f, 0.f, 0.f);
        int gr = bm + a_row;
        if (gr < M)
            av = *reinterpret_cast<const float4*>(A + (long)gr * K + kt + a_k4 * 4);
        As[a_k4 * 4 + 0][a_row] = av.x;
        As[a_k4 * 4 + 1][a_row] = av.y;
        As[a_k4 * 4 + 2][a_row] = av.z;
        As[a_k4 * 4 + 3][a_row] = av.w;
        float4 bv = *reinterpret_cast<const float4*>(B + (long)(kt + b_kr) * D_H + bn + b_c4 * 4);
        *reinterpret_cast<float4*>(&Bs[b_kr][b_c4 * 4]) = bv;
        __syncthreads();

#pragma unroll
        for (int k = 0; k < 16; k++) {
            float a[4], b[4];
#pragma unroll
            for (int i = 0; i < 4; i++) a[i] = As[k][ty * 4 + i];
#pragma unroll
            for (int j = 0; j < 4; j++) b[j] = Bs[k][tx * 4 + j];
#pragma unroll
            for (int i = 0; i < 4; i++)
#pragma unroll
                for (int j = 0; j < 4; j++) acc[i][j] += a[i] * b[j];
        }
        __syncthreads();
    }

#pragma unroll
    for (int i = 0; i < 4; i++) {
        int row = bm + ty * 4 + i;
        if (row < M) {
#pragma unroll
            for (int j = 0; j < 4; j++) {
                int col = bn + tx * 4 + j;
                float v = acc[i][j];
                if (HAS_BIAS) v += bias[col];
                C[(long)row * D_H + col] = v;
            }
        }
    }
}

// ---------------- edge scatter: agg[dst] += norm * feat[src] ----------------
// one warp per edge; 64 float4 per row -> 2 per lane; vector red (no return)
__global__ void scatter_kernel(const int* __restrict__ src,
                               const int* __restrict__ dst,
                               const float* __restrict__ w,
                               const float* __restrict__ feat,
                               int E) {
    int gw = (blockIdx.x * blockDim.x + threadIdx.x) >> 5;
    int lane = threadIdx.x & 31;
    int nw = (gridDim.x * blockDim.x) >> 5;
    for (int e = gw; e < E; e += nw) {
        int s = src[e];
        int d = dst[e];
        float n = g_dinv[s] * w[e] * g_dinv[d];
        const float4* fs = reinterpret_cast<const float4*>(feat + (long)s * D_H);
        float4* fd = reinterpret_cast<float4*>(g_agg + (long)d * D_H);
#pragma unroll
        for (int i = 0; i < 2; i++) {
            float4 v = fs[lane + i * 32];
            red_add_v4(&fd[lane + i * 32],
                       make_float4(v.x * n, v.y * n, v.z * n, v.w * n));
        }
    }
}

// ---------------- block-wide mean/var helper ----------------
__device__ __forceinline__ void block_stats(float t, float& mu, float& var) {
    float s = t, sq = t * t;
#pragma unroll
    for (int o = 16; o; o >>= 1) {
        s  += __shfl_xor_sync(0xFFFFFFFFu, s, o);
        sq += __shfl_xor_sync(0xFFFFFFFFu, sq, o);
    }
    __shared__ float ss[8], ssq[8];
    int wid = threadIdx.x >> 5;
    if ((threadIdx.x & 31) == 0) { ss[wid] = s; ssq[wid] = sq; }
    __syncthreads();
    float ts = 0.f, tq = 0.f;
#pragma unroll
    for (int i = 0; i < 8; i++) { ts += ss[i]; tq += ssq[i]; }
    mu = ts * (1.0f / D_H);
    var = tq * (1.0f / D_H) - mu * mu;
}

// ---------------- LN1: h = LN(hres + relu(agg + dinv^2*h1 + b1)) ------------
// also re-zeros agg for hop 1
__global__ void ln1_kernel(const float* __restrict__ b1,
                           const float* __restrict__ gamma,
                           const float* __restrict__ beta) {
    int row = blockIdx.x;
    int c = threadIdx.x;
    long idx = (long)row * D_H + c;
    float di = g_dinv[row];
    float a = g_agg[idx] + di * di * g_h1[idx] + b1[c];
    g_agg[idx] = 0.0f;                      // reset for hop 1
    float t = g_hres[idx] + fmaxf(a, 0.0f);
    float mu, var;
    block_stats(t, mu, var);
    g_h[idx] = (t - mu) * rsqrtf(var + LN_EPS) * gamma[c] + beta[c];
}

// ---------------- LN2: out = LN(h + agg + dinv^2*h2 + b2) -------------------
__global__ void ln2_kernel(const float* __restrict__ b2,
                           const float* __restrict__ gamma,
                           const float* __restrict__ beta,
                           float* __restrict__ out) {
    int row = blockIdx.x;
    int c = threadIdx.x;
    long idx = (long)row * D_H + c;
    float di = g_dinv[row];
    float t = g_h[idx] + g_agg[idx] + di * di * g_h1[idx] + b2[c];
    float mu, var;
    block_stats(t, mu, var);
    out[idx] = (t - mu) * rsqrtf(var + LN_EPS) * gamma[c] + beta[c];
}

// ---------------- launch ----------------
extern "C" void kernel_launch(void* const* d_in, const int* in_sizes, int n_in,
                              void* d_out, int out_size) {
    const float* x      = (const float*)d_in[0];   // [20000,128]
    const int*   ei     = (const int*)d_in[1];     // [2,E] int32
    const float* ew     = (const float*)d_in[2];   // [E]
    const float* W1     = (const float*)d_in[3];
    const float* b1     = (const float*)d_in[4];
    const float* W2     = (const float*)d_in[5];
    const float* b2     = (const float*)d_in[6];
    const float* Wres   = (const float*)d_in[7];
    const float* bres   = (const float*)d_in[8];
    const float* gamma1 = (const float*)d_in[9];
    const float* beta1  = (const float*)d_in[10];
    const float* gamma2 = (const float*)d_in[11];
    const float* beta2  = (const float*)d_in[12];
    float* out = (float*)d_out;

    const int E = in_sizes[2];        // edge_weight element count
    const int* src = ei;
    const int* dst = ei + E;

    // TRUE device addresses of the scratch symbols (host-side name would be
    // the host shadow, which ATS silently makes "work" — wrongly).
    float *p_h1 = nullptr, *p_hres = nullptr, *p_h = nullptr;
    cudaGetSymbolAddress((void**)&p_h1,   g_h1);
    cudaGetSymbolAddress((void**)&p_hres, g_hres);
    cudaGetSymbolAddress((void**)&p_h,    g_h);

    init_kernel<<<1024, 256>>>();
    deg_kernel<<<(E + 255) / 256, 256>>>(dst, ew, E);
    dinv_kernel<<<(N_NODES + 255) / 256, 256>>>();

    dim3 gemm_grid((N_NODES + 63) / 64, D_H / 64);
    // h1 = x @ W1 ; hres = x @ Wres + bres
    sgemm_kernel<D_IN, false><<<gemm_grid, 256>>>(x, W1, nullptr, p_h1, N_NODES);
    sgemm_kernel<D_IN, true ><<<gemm_grid, 256>>>(x, Wres, bres, p_hres, N_NODES);

    scatter_kernel<<<2048, 256>>>(src, dst, ew, p_h1, E);
    ln1_kernel<<<N_NODES, D_H>>>(b1, gamma1, beta1);

    // h2 = h @ W2  (reuse g_h1)
    sgemm_kernel<D_H, false><<<gemm_grid, 256>>>(p_h, W2, nullptr, p_h1, N_NODES);
    scatter_kernel<<<2048, 256>>>(src, dst, ew, p_h1, E);
    ln2_kernel<<<N_NODES, D_H>>>(b2, gamma2, beta2, out);
}